// round 17
// baseline (speedup 1.0000x reference)
#include <cuda_runtime.h>
#include <cuda_bf16.h>
#include <math.h>

// Shapes (fixed): B=2, T=512, D=256, H=8, c=32
#define NTOK 1024
#define DM   256
#define NH   8
#define HC   32
#define T    512
#define KSPLIT 8

__device__ float g_qkv [NTOK * 3 * DM];          // 1024 x 768
__device__ float g_x1  [NTOK * DM];              // 1024 x 256
__device__ float g_h   [NTOK * 4 * DM];          // 1024 x 1024

__device__ __forceinline__ void cp16(void* smem_dst, const void* gsrc) {
    unsigned s = (unsigned)__cvta_generic_to_shared(smem_dst);
    asm volatile("cp.async.cg.shared.global [%0], [%1], 16;\n" :: "r"(s), "l"(gsrc));
}

__device__ __forceinline__ void red2(float* gaddr, float v0, float v1) {
    asm volatile("red.global.add.v2.f32 [%0], {%1, %2};\n"
                 :: "l"(gaddr), "f"(v0), "f"(v1) : "memory");
}

// packed f32x2 helpers (sm_100+)
__device__ __forceinline__ unsigned long long addx2(unsigned long long a, unsigned long long b) {
    unsigned long long d;
    asm("add.rn.f32x2 %0, %1, %2;" : "=l"(d) : "l"(a), "l"(b));
    return d;
}
__device__ __forceinline__ void unpack2(unsigned long long v, float& lo, float& hi) {
    asm("mov.b64 {%0, %1}, %2;" : "=f"(lo), "=f"(hi) : "l"(v));
}

// ---------------------------------------------------------------------------
// TF32 tensor-core GEMM, STAGES-deep cp.async pipeline, split-K via blockIdx.z.
// BM=64, BN=64, BK=32, 256 threads, warp tile 32x16.
// STAGES=3 for nt=4 loops, 4 for nt=8. RED=true: vector REDG into seeded C.
// ---------------------------------------------------------------------------
template<int ACT, bool RES, bool RED, bool DEP, int STAGES>
__global__ void gemm_tc(const float* __restrict__ A, const float* __restrict__ B,
                        const float* __restrict__ bias, const float* __restrict__ res,
                        float* __restrict__ C, int M, int N, int Klen, int lda)
{
    __shared__ float As[STAGES][64 * 36];
    __shared__ float Bs[STAGES][32 * 68];

    const int tid  = threadIdx.x;
    const int w    = tid >> 5;
    const int lane = tid & 31;
    const int g    = lane >> 2;
    const int tg   = lane & 3;
    const int warpM = w >> 2;
    const int warpN = w & 3;

    const int row0 = blockIdx.y * 64;
    const int col0 = blockIdx.x * 64;

    const int kz = blockIdx.z * Klen;
    A += kz;
    B += (size_t)kz * N;

    float acc[2][2][4] = {};

    auto loadA = [&](int k0, int buf) {
        #pragma unroll
        for (int c = tid; c < 512; c += 256) {
            int rA = c >> 3, cA = (c & 7) * 4;
            cp16(&As[buf][rA * 36 + cA], A + (size_t)(row0 + rA) * lda + k0 + cA);
        }
    };
    auto loadB = [&](int k0, int buf) {
        #pragma unroll
        for (int c = tid; c < 512; c += 256) {
            int rB = c >> 4, cB = (c & 15) * 4;
            cp16(&Bs[buf][rB * 68 + cB], B + (size_t)(k0 + rB) * N + col0 + cB);
        }
    };

    const int nt = Klen >> 5;
    constexpr int PRE = STAGES - 1;

    #pragma unroll
    for (int s = 0; s < PRE; s++) loadB(s << 5, s);
    if (DEP) cudaGridDependencySynchronize();
    #pragma unroll
    for (int s = 0; s < PRE; s++) {
        loadA(s << 5, s);
        asm volatile("cp.async.commit_group;\n");
    }

    for (int i = 0; i < nt; i++) {
        if (i + PRE < nt) {
            loadB((i + PRE) << 5, (i + PRE) % STAGES);
            loadA((i + PRE) << 5, (i + PRE) % STAGES);
            asm volatile("cp.async.commit_group;\n");
            asm volatile("cp.async.wait_group %0;\n" :: "n"(PRE));
        } else if (i + 2 < nt && PRE >= 3) {
            asm volatile("cp.async.wait_group 2;\n");
        } else if (i + 1 < nt) {
            asm volatile("cp.async.wait_group 1;\n");
        } else {
            asm volatile("cp.async.wait_group 0;\n");
        }
        __syncthreads();

        const float* Ab = As[i % STAGES];
        const float* Bb = Bs[i % STAGES];

        #pragma unroll
        for (int ks = 0; ks < 4; ks++) {
            const int kk = ks * 8;
            unsigned a[2][4], b[2][2];
            #pragma unroll
            for (int ii = 0; ii < 2; ii++) {
                const int rb = warpM * 32 + ii * 16;
                a[ii][0] = __float_as_uint(Ab[(rb + g    ) * 36 + kk + tg    ]);
                a[ii][1] = __float_as_uint(Ab[(rb + g + 8) * 36 + kk + tg    ]);
                a[ii][2] = __float_as_uint(Ab[(rb + g    ) * 36 + kk + tg + 4]);
                a[ii][3] = __float_as_uint(Ab[(rb + g + 8) * 36 + kk + tg + 4]);
            }
            #pragma unroll
            for (int j = 0; j < 2; j++) {
                const int cb = warpN * 16 + j * 8;
                b[j][0] = __float_as_uint(Bb[(kk + tg    ) * 68 + cb + g]);
                b[j][1] = __float_as_uint(Bb[(kk + tg + 4) * 68 + cb + g]);
            }
            #pragma unroll
            for (int ii = 0; ii < 2; ii++)
                #pragma unroll
                for (int j = 0; j < 2; j++) {
                    asm volatile(
                        "mma.sync.aligned.m16n8k8.row.col.f32.tf32.tf32.f32 "
                        "{%0,%1,%2,%3}, {%4,%5,%6,%7}, {%8,%9}, {%0,%1,%2,%3};"
                        : "+f"(acc[ii][j][0]), "+f"(acc[ii][j][1]),
                          "+f"(acc[ii][j][2]), "+f"(acc[ii][j][3])
                        : "r"(a[ii][0]), "r"(a[ii][1]), "r"(a[ii][2]), "r"(a[ii][3]),
                          "r"(b[j][0]), "r"(b[j][1]));
                }
        }
        __syncthreads();
    }

    #pragma unroll
    for (int ii = 0; ii < 2; ii++) {
        const int rb = row0 + warpM * 32 + ii * 16;
        #pragma unroll
        for (int j = 0; j < 2; j++) {
            const int cb = col0 + warpN * 16 + j * 8;
            #pragma unroll
            for (int rg = 0; rg < 2; rg++) {
                const int r = rb + g + rg * 8;
                const int c = cb + tg * 2;
                float v0 = acc[ii][j][rg * 2 + 0];
                float v1 = acc[ii][j][rg * 2 + 1];
                if (RED) {
                    red2(&C[(size_t)r * N + c], v0, v1);
                } else {
                    v0 += bias[c];
                    v1 += bias[c + 1];
                    if (ACT == 1) {
                        v0 = v0 * __fdividef(1.f, 1.f + __expf(-1.702f * v0));
                        v1 = v1 * __fdividef(1.f, 1.f + __expf(-1.702f * v1));
                    }
                    if (RES) {
                        float2 rv = *(const float2*)&res[(size_t)r * N + c];
                        v0 += rv.x; v1 += rv.y;
                    }
                    float2 o; o.x = v0; o.y = v1;
                    *(float2*)&C[(size_t)r * N + c] = o;
                }
            }
        }
    }
    cudaTriggerProgrammaticLaunchCompletion();   // after stores
}

// ---------------------------------------------------------------------------
// L1-distance attention + residual. 128 blocks x 512 threads (16 warps).
// DOUBLE-BUFFERED P: phase A of chunk ch+1 is issued in the same barrier
// interval as phase B of chunk ch (fma work overlaps tensor work); one
// __syncthreads per chunk instead of two.
// Epilogue writes x1 = x + attn AND seeds out = x1 + b_proj.
// ---------------------------------------------------------------------------
#define ATTN_SMEM 223488
__global__ void attn_kernel(const float* __restrict__ x, const float* __restrict__ qkv,
                            const float* __restrict__ b_proj,
                            float* __restrict__ x1, float* __restrict__ outseed)
{
    extern __shared__ float sh[];
    float* Kneg = sh;                    // [512][32]  16384 floats
    float* Vsh  = sh + 16384;            // [512][40]  20480 floats
    float* Psh0 = sh + 36864;            // [128][72]   9216 floats
    float* Psh1 = sh + 46080;            // [128][72]   9216 floats
    float* lbuf = sh + 55296;            // [64][8]
    float* Linv = sh + 55808;            // [64]

    const int bid = blockIdx.x;
    const int bh  = bid >> 3;
    const int qb  = bid & 7;
    const int b   = bh >> 3;
    const int hh  = bh & 7;
    const int tid = threadIdx.x;
    const int w   = tid >> 5;
    const int lane = tid & 31;
    const int t0  = qb * 64;

    const int qg = w & 1;
    const int ss = w >> 1;
    const int q  = qg * 32 + lane;
    const int t  = t0 + q;

    const int g  = lane >> 2;
    const int tg = lane & 3;
    const int mi = w >> 2;
    const int nj = w & 3;

    const float* qkv_bh = qkv + (size_t)b * T * 768 + hh * 96;

    cudaGridDependencySynchronize();     // qkv must be complete

    for (int i = tid; i < 4096; i += 512) {
        int s = i >> 3, j = i & 7;
        uint4 kv = *(const uint4*)(qkv_bh + (size_t)s * 768 + 32 + j * 4);
        kv.x ^= 0x80000000u; kv.y ^= 0x80000000u;
        kv.z ^= 0x80000000u; kv.w ^= 0x80000000u;
        *(uint4*)(Kneg + s * 32 + j * 4) = kv;
        *(float4*)(Vsh + s * 40 + j * 4) =
            *(const float4*)(qkv_bh + (size_t)s * 768 + 64 + j * 4);
    }

    unsigned long long q2[16];
    {
        const ulonglong2* qsrc = (const ulonglong2*)(qkv_bh + (size_t)t * 768);
        #pragma unroll
        for (int j = 0; j < 8; j++) {
            ulonglong2 v = qsrc[j];
            q2[2 * j] = v.x; q2[2 * j + 1] = v.y;
        }
    }

    const float scale = 0.1767766952966369f;
    const unsigned long long ABSM = 0x7FFFFFFF7FFFFFFFULL;
    float l = 0.f;
    float acc[4] = {};

    // Phase A for chunk ch -> Pdst
    auto phaseA = [&](int ch, float* Pdst) {
        #pragma unroll 2
        for (int i2 = 0; i2 < 16; i2++) {
            const int kc = ss * 16 + i2;
            const int sg = ch * 128 + kc;
            const ulonglong2* krow = (const ulonglong2*)(Kneg + sg * 32);
            unsigned long long accA = 0ULL, accB = 0ULL;
            #pragma unroll
            for (int j = 0; j < 8; j++) {
                ulonglong2 kk = krow[j];
                unsigned long long d0 = addx2(q2[2 * j],     kk.x) & ABSM;
                unsigned long long d1 = addx2(q2[2 * j + 1], kk.y) & ABSM;
                accA = addx2(accA, d0);
                accB = addx2(accB, d1);
            }
            float a0, a1, b0, b1;
            unpack2(accA, a0, a1);
            unpack2(accB, b0, b1);
            float dist = (a0 + a1) + (b0 + b1);
            float wgt = (sg == t) ? 0.f : __fdividef(1.f, 0.001f + dist * scale);
            float p = __expf(wgt);
            l += p;
            Pdst[kc * 72 + q] = p;
        }
    };

    // Phase B: O += P @ V_chunk
    auto phaseB = [&](int ch, const float* Psrc) {
        const float* Vch = Vsh + ch * 128 * 40;
        #pragma unroll
        for (int ks = 0; ks < 16; ks++) {
            const int kk = ks * 8;
            unsigned a0 = __float_as_uint(Psrc[(kk + tg    ) * 72 + mi * 16 + g    ]);
            unsigned a1 = __float_as_uint(Psrc[(kk + tg    ) * 72 + mi * 16 + g + 8]);
            unsigned a2 = __float_as_uint(Psrc[(kk + tg + 4) * 72 + mi * 16 + g    ]);
            unsigned a3 = __float_as_uint(Psrc[(kk + tg + 4) * 72 + mi * 16 + g + 8]);
            unsigned b0 = __float_as_uint(Vch[(kk + tg    ) * 40 + nj * 8 + g]);
            unsigned b1 = __float_as_uint(Vch[(kk + tg + 4) * 40 + nj * 8 + g]);
            asm volatile(
                "mma.sync.aligned.m16n8k8.row.col.f32.tf32.tf32.f32 "
                "{%0,%1,%2,%3}, {%4,%5,%6,%7}, {%8,%9}, {%0,%1,%2,%3};"
                : "+f"(acc[0]), "+f"(acc[1]), "+f"(acc[2]), "+f"(acc[3])
                : "r"(a0), "r"(a1), "r"(a2), "r"(a3), "r"(b0), "r"(b1));
        }
    };

    __syncthreads();          // K/V staged
    phaseA(0, Psh0);
    __syncthreads();          // P0 ready

    phaseA(1, Psh1);          // fma work ...
    phaseB(0, Psh0);          // ... overlaps tensor work in issue stream
    __syncthreads();          // P1 ready, P0 fully consumed

    phaseA(2, Psh0);
    phaseB(1, Psh1);
    __syncthreads();

    phaseA(3, Psh1);
    phaseB(2, Psh0);
    __syncthreads();

    phaseB(3, Psh1);

    lbuf[q * 8 + ss] = l;
    __syncthreads();
    if (tid < 64) {
        float L = 0.f;
        #pragma unroll
        for (int i = 0; i < 8; i++) L += lbuf[tid * 8 + i];
        Linv[tid] = __fdividef(1.f, L);
    }
    __syncthreads();

    // Epilogue: x1 = x + attn ; outseed = x1 + b_proj (proj REDs on top)
    {
        const int c0 = nj * 8 + tg * 2;
        float2 bp = *(const float2*)&b_proj[hh * HC + c0];
        #pragma unroll
        for (int rg = 0; rg < 2; rg++) {
            const int r = mi * 16 + g + rg * 8;
            float inv = Linv[r];
            size_t idx = ((size_t)b * T + (t0 + r)) * DM + hh * HC + c0;
            float2 xv = *(const float2*)&x[idx];
            float2 o;
            o.x = xv.x + acc[rg * 2 + 0] * inv;
            o.y = xv.y + acc[rg * 2 + 1] * inv;
            *(float2*)&x1[idx] = o;
            float2 osd; osd.x = o.x + bp.x; osd.y = o.y + bp.y;
            *(float2*)&outseed[idx] = osd;
        }
    }
    cudaTriggerProgrammaticLaunchCompletion();   // after stores
}

// ---------------------------------------------------------------------------
template<typename K, typename... Args>
static void launch_pdl(K kernel, dim3 grid, dim3 block, unsigned smem, Args... args)
{
    cudaLaunchAttribute attr[1];
    attr[0].id = cudaLaunchAttributeProgrammaticStreamSerialization;
    attr[0].val.programmaticStreamSerializationAllowed = 1;
    cudaLaunchConfig_t cfg{};
    cfg.gridDim = grid;
    cfg.blockDim = block;
    cfg.dynamicSmemBytes = smem;
    cfg.stream = 0;
    cfg.attrs = attr;
    cfg.numAttrs = 1;
    cudaLaunchKernelEx(&cfg, kernel, args...);
}

extern "C" void kernel_launch(void* const* d_in, const int* in_sizes, int n_in,
                              void* d_out, int out_size)
{
    const float* x      = (const float*)d_in[0];
    const float* W_qkv  = (const float*)d_in[1];
    const float* b_qkv  = (const float*)d_in[2];
    const float* W_fc   = (const float*)d_in[3];
    const float* b_fc   = (const float*)d_in[4];
    const float* W_proj = (const float*)d_in[5];
    const float* b_proj = (const float*)d_in[6];
    float* out = (float*)d_out;

    float *p_qkv, *p_x1, *p_h;
    cudaGetSymbolAddress((void**)&p_qkv,  g_qkv);
    cudaGetSymbolAddress((void**)&p_x1,   g_x1);
    cudaGetSymbolAddress((void**)&p_h,    g_h);

    static bool cfgd = false;
    if (!cfgd) {
        cudaFuncSetAttribute(attn_kernel, cudaFuncAttributeMaxDynamicSharedMemorySize, ATTN_SMEM);
        cfgd = true;
    }

    // 1) qkv = x @ W_qkv + b_qkv            (1024 x 768, K=256, nt=8) 4-stage
    launch_pdl(gemm_tc<0, false, false, false, 4>, dim3(12, 16), dim3(256), 0,
               x, W_qkv, b_qkv, (const float*)nullptr, p_qkv, NTOK, 3 * DM, DM, DM);

    // 2) x1 = x + attention(qkv); out seeded with x1 + b_proj
    launch_pdl(attn_kernel, dim3(128), dim3(512), ATTN_SMEM,
               x, p_qkv, b_proj, p_x1, out);

    // 3) h = quick_gelu(x1 @ W_fc + b_fc)   (1024 x 1024, K=256, nt=8) 4-stage
    launch_pdl(gemm_tc<1, false, false, true, 4>, dim3(16, 16), dim3(256), 0,
               p_x1, W_fc, b_fc, (const float*)nullptr, p_h, NTOK, 4 * DM, DM, DM);

    // 4) out += h @ W_proj via vector REDG, split-K x8 (nt=4) 3-stage
    launch_pdl(gemm_tc<0, false, true, true, 3>, dim3(4, 16, KSPLIT), dim3(256), 0,
               p_h, W_proj, (const float*)nullptr, (const float*)nullptr,
               out, NTOK, DM, 1024 / KSPLIT, 4 * DM);
}